// round 16
// baseline (speedup 1.0000x reference)
#include <cuda_runtime.h>
#include <cuda_fp16.h>

#define TOTAL 131072
#define NNODE 4096
#define HD 256

// ---------------- scratch (device globals) ----------------------------------
__device__ __half  g_ha[TOTAL * HD];    // activations, ping
__device__ __half  g_hb[TOTAL * HD];    // activations, pong
__device__ __half  g_wh[3 * HD * HD];   // W (fp16), layers 1..3, layout [k][n]
__device__ float   g_u [HD];            // proj_w @ W0
__device__ float   g_w0[HD];            // proj_b @ W0
__device__ float   g_part[2048 * HD];   // per-block column sums (layer 3)
__device__ float4  g_wt4[NNODE];        // edge weights fp32 (for k0)
__device__ float   g_ws [NNODE];        // self weight fp32 (for k0)
__device__ uint2   g_wph[NNODE];        // edge weights packed fp16 {x,y,z,w}
__device__ __half  g_wsh[NNODE];        // self weight fp16

// ---------------- helpers ----------------------------------------------------
__device__ __forceinline__ float degf(int n) {
    int c = n % 65;
    return (float)(1 + (int)((c != 64) && (n < 4095)) + (int)(c != 0)
                     + (int)(n < 4031) + (int)(n >= 65));
}
__device__ __forceinline__ void cp16ca(unsigned int dst, const void* src) {
    asm volatile("cp.async.ca.shared.global [%0], [%1], 16;\n" :: "r"(dst), "l"(src));
}
__device__ __forceinline__ void ldm4(unsigned int* r, unsigned int a) {
    asm volatile("ldmatrix.sync.aligned.m8n8.x4.shared.b16 {%0,%1,%2,%3}, [%4];\n"
                 : "=r"(r[0]), "=r"(r[1]), "=r"(r[2]), "=r"(r[3]) : "r"(a));
}
__device__ __forceinline__ void ldm4t(unsigned int* r, unsigned int a) {
    asm volatile("ldmatrix.sync.aligned.m8n8.x4.trans.shared.b16 {%0,%1,%2,%3}, [%4];\n"
                 : "=r"(r[0]), "=r"(r[1]), "=r"(r[2]), "=r"(r[3]) : "r"(a));
}
__device__ __forceinline__ void mma16816(float* d, const unsigned int* a, const unsigned int* b) {
    asm volatile(
        "mma.sync.aligned.m16n8k16.row.col.f32.f16.f16.f32 "
        "{%0,%1,%2,%3}, {%4,%5,%6,%7}, {%8,%9}, {%0,%1,%2,%3};\n"
        : "+f"(d[0]), "+f"(d[1]), "+f"(d[2]), "+f"(d[3])
        : "r"(a[0]), "r"(a[1]), "r"(a[2]), "r"(a[3]), "r"(b[0]), "r"(b[1]));
}
// half2 stencil tap: v += w * tap8
__device__ __forceinline__ void sten8(const __half* __restrict__ p, __half2* v, __half2 w) {
    uint4 A = *(const uint4*)p;
    const __half2* ah = (const __half2*)&A;
    v[0] = __hfma2(w, ah[0], v[0]);
    v[1] = __hfma2(w, ah[1], v[1]);
    v[2] = __hfma2(w, ah[2], v[2]);
    v[3] = __hfma2(w, ah[3], v[3]);
}

// ---------------- merged prep kernel ------------------------------------------
__global__ void prep_all(const float* __restrict__ pw, const float* __restrict__ pb,
                         const float* __restrict__ cw) {
    int bid = blockIdx.x;
    if (bid < 256) {
        int c = bid, k = threadIdx.x;
        float wv = cw[k * HD + c];
        float u = pw[k] * wv, w = pb[k] * wv;
        #pragma unroll
        for (int o = 16; o > 0; o >>= 1) {
            u += __shfl_xor_sync(0xffffffffu, u, o);
            w += __shfl_xor_sync(0xffffffffu, w, o);
        }
        __shared__ float ru[8], rw[8];
        int wid = k >> 5;
        if ((k & 31) == 0) { ru[wid] = u; rw[wid] = w; }
        __syncthreads();
        if (k == 0) {
            float tu = 0.f, tw = 0.f;
            #pragma unroll
            for (int i = 0; i < 8; i++) { tu += ru[i]; tw += rw[i]; }
            g_u[c] = tu; g_w0[c] = tw;
        }
    } else if (bid < 1024) {
        int idx = (bid - 256) * 256 + threadIdx.x;
        g_wh[idx] = __float2half_rn(cw[HD * HD + idx]);
    } else {
        int n = (bid - 1024) * 256 + threadIdx.x;
        int col = n % 65;
        float dn = degf(n), dinv = rsqrtf(dn);
        float4 w;
        w.x = (col != 64 && n < 4095) ? dinv * rsqrtf(degf(n + 1))  : 0.f;
        w.y = (col != 0)              ? dinv * rsqrtf(degf(n - 1))  : 0.f;
        w.z = (n < 4031)              ? dinv * rsqrtf(degf(n + 65)) : 0.f;
        w.w = (n >= 65)               ? dinv * rsqrtf(degf(n - 65)) : 0.f;
        g_wt4[n] = w;
        g_ws[n]  = 1.f / dn;
        __half2 lo = __halves2half2(__float2half_rn(w.x), __float2half_rn(w.y));
        __half2 hi = __halves2half2(__float2half_rn(w.z), __float2half_rn(w.w));
        uint2 p;
        p.x = *(unsigned int*)&lo;
        p.y = *(unsigned int*)&hi;
        g_wph[n] = p;
        g_wsh[n] = __float2half_rn(1.f / dn);
    }
}

// ---------------- layer 0: warp handles 16 rows; per-row coeffs lane-parallel
__global__ void __launch_bounds__(256) k0(const float* __restrict__ x,
                                          const float* __restrict__ cb,
                                          const float* __restrict__ lg,
                                          const float* __restrict__ lb) {
    int warp = threadIdx.x >> 5, lane = threadIdx.x & 31;
    int c8 = lane * 8;
    int row0 = blockIdx.x * 128 + warp * 16;

    float ua[8], wa[8], ba[8], ga[8], la[8];
    {
        float4 t0 = *(const float4*)(g_u  + c8), t1 = *(const float4*)(g_u  + c8 + 4);
        ua[0]=t0.x; ua[1]=t0.y; ua[2]=t0.z; ua[3]=t0.w; ua[4]=t1.x; ua[5]=t1.y; ua[6]=t1.z; ua[7]=t1.w;
        t0 = *(const float4*)(g_w0 + c8); t1 = *(const float4*)(g_w0 + c8 + 4);
        wa[0]=t0.x; wa[1]=t0.y; wa[2]=t0.z; wa[3]=t0.w; wa[4]=t1.x; wa[5]=t1.y; wa[6]=t1.z; wa[7]=t1.w;
        t0 = *(const float4*)(cb   + c8); t1 = *(const float4*)(cb   + c8 + 4);
        ba[0]=t0.x; ba[1]=t0.y; ba[2]=t0.z; ba[3]=t0.w; ba[4]=t1.x; ba[5]=t1.y; ba[6]=t1.z; ba[7]=t1.w;
        t0 = *(const float4*)(lg   + c8); t1 = *(const float4*)(lg   + c8 + 4);
        ga[0]=t0.x; ga[1]=t0.y; ga[2]=t0.z; ga[3]=t0.w; ga[4]=t1.x; ga[5]=t1.y; ga[6]=t1.z; ga[7]=t1.w;
        t0 = *(const float4*)(lb   + c8); t1 = *(const float4*)(lb   + c8 + 4);
        la[0]=t0.x; la[1]=t0.y; la[2]=t0.z; la[3]=t0.w; la[4]=t1.x; la[5]=t1.y; la[6]=t1.z; la[7]=t1.w;
    }

    float Av = 0.f, Bv = 0.f;
    if (lane < 16) {
        int row = row0 + lane;
        int n = row & (NNODE - 1);
        float4 wt = g_wt4[n];
        float ws = g_ws[n];
        Av = x[row] * ws; Bv = ws;
        if (wt.x != 0.f) { Av += wt.x * x[row + 1];  Bv += wt.x; }
        if (wt.y != 0.f) { Av += wt.y * x[row - 1];  Bv += wt.y; }
        if (wt.z != 0.f) { Av += wt.z * x[row + 65]; Bv += wt.z; }
        if (wt.w != 0.f) { Av += wt.w * x[row - 65]; Bv += wt.w; }
    }

    #pragma unroll 4
    for (int rr = 0; rr < 16; rr++) {
        int row = row0 + rr;
        float A = __shfl_sync(0xffffffffu, Av, rr);
        float B = __shfl_sync(0xffffffffu, Bv, rr);

        float y[8], s1 = 0.f, s2 = 0.f;
        #pragma unroll
        for (int j = 0; j < 8; j++) {
            y[j] = A * ua[j] + B * wa[j] + ba[j];
            s1 += y[j]; s2 += y[j] * y[j];
        }
        #pragma unroll
        for (int o = 16; o > 0; o >>= 1) {
            s1 += __shfl_xor_sync(0xffffffffu, s1, o);
            s2 += __shfl_xor_sync(0xffffffffu, s2, o);
        }
        float mu  = s1 * (1.f / 256.f);
        float var = s2 * (1.f / 256.f) - mu * mu;
        float rs  = rsqrtf(var + 1e-5f);

        uint4 Hq;
        __half* hp = (__half*)&Hq;
        #pragma unroll
        for (int j = 0; j < 8; j++) {
            float v = fmaxf((y[j] - mu) * rs * ga[j] + la[j], 0.f);
            hp[j] = __float2half_rn(v);
        }
        *(uint4*)(g_ha + (size_t)row * HD + c8) = Hq;
    }
}

// ---------------- fused stencil + GEMM + bias + LN + ReLU (+pool) -----------
// M=64 tile, 256 threads, 8 warps (warp tile 32x64), 2 CTAs/SM.
// A = stencil(hin) in smem (packed HFMA2); B streamed in 4 K-chunks of 64 rows
// via 2-stage cp.async (4 barriers/tile). Epilogue stores staged via smem.
#define A_OFF    0
#define ABLK     5120           /* bytes per 64x40-half A k-block (8 blocks) */
#define B_OFF    40960
#define LDB      264
#define BSTG     33792          /* 64 x 264 halves */
#define ST1_OFF  108544         /* [4][64] floats */
#define ST2_OFF  109568
#define POOL_OFF 110592         /* [2][256] floats */
#define SMEM_BYTES 112640

__device__ __forceinline__ void load_B(unsigned int sb, int tid, int wsel,
                                       int kc, int s) {
    const __half* Bw = g_wh + (size_t)wsel * HD * HD + (size_t)kc * 64 * HD;
    unsigned int st = sb + B_OFF + s * BSTG;
    #pragma unroll
    for (int i = 0; i < 8; i++) {
        int ch = tid + i * 256;            // 0..2047
        int kr = ch >> 5, cg = ch & 31;
        cp16ca(st + (unsigned)(kr * LDB + cg * 8) * 2, Bw + kr * HD + cg * 8);
    }
    asm volatile("cp.async.commit_group;\n" ::);
}

__global__ void __launch_bounds__(256, 2) gemm_fused(int wsel, int mode, int dir,
                                                     const float* __restrict__ cb,
                                                     const float* __restrict__ lg,
                                                     const float* __restrict__ lb) {
    extern __shared__ char smraw[];
    unsigned int sb = (unsigned int)__cvta_generic_to_shared(smraw);
    float* st1  = (float*)(smraw + ST1_OFF);   // [4][64]
    float* st2  = (float*)(smraw + ST2_OFF);   // [4][64]
    float* pool = (float*)(smraw + POOL_OFF);  // [2][256]
    int tid = threadIdx.x, lane = tid & 31, warp = tid >> 5;
    int m0 = blockIdx.x * 64;
    int wm = (warp & 1) * 32, wn = (warp >> 1) * 64;

    const __half* __restrict__ hin = dir ? g_hb : g_ha;
    __half* __restrict__ hout      = dir ? g_ha : g_hb;

    // ---- B pipeline prologue (chunk 0 -> stage 0; overlaps stencil) ----
    load_B(sb, tid, wsel, 0, 0);

    // ---- A = stencil(hin) into smem, packed fp16 math ----
    #pragma unroll
    for (int i = 0; i < 8; i++) {
        int ch = tid + i * 256;              // 0..2047
        int r = ch >> 5, cg = ch & 31;       // warp-uniform r
        int row = m0 + r;
        int n = row & (NNODE - 1);
        uint2 wp = g_wph[n];
        __half2 wxy = *(__half2*)&wp.x;
        __half2 wzw = *(__half2*)&wp.y;
        size_t cofs = (size_t)cg * 8;
        const __half* hr = hin + (size_t)row * HD + cofs;
        const __half* hx = hin + (size_t)min(row + 1,  TOTAL - 1) * HD + cofs;
        const __half* hy = hin + (size_t)max(row - 1,  0)         * HD + cofs;
        const __half* hz = hin + (size_t)min(row + 65, TOTAL - 1) * HD + cofs;
        const __half* hw = hin + (size_t)max(row - 65, 0)         * HD + cofs;

        __half2 vh[4];
        {
            uint4 A = *(const uint4*)hr;
            const __half2* ah = (const __half2*)&A;
            __half2 w2 = __half2half2(g_wsh[n]);
            vh[0] = __hmul2(w2, ah[0]); vh[1] = __hmul2(w2, ah[1]);
            vh[2] = __hmul2(w2, ah[2]); vh[3] = __hmul2(w2, ah[3]);
        }
        sten8(hx, vh, __half2half2(__low2half(wxy)));
        sten8(hy, vh, __half2half2(__high2half(wxy)));
        sten8(hz, vh, __half2half2(__low2half(wzw)));
        sten8(hw, vh, __half2half2(__high2half(wzw)));

        int kb = cg >> 2, cc = (cg & 3) * 8;
        *(uint4*)(smraw + A_OFF + kb * ABLK + (r * 40 + cc) * 2) = *(uint4*)vh;
    }

    // ---- mainloop: 4 K-chunks of 64, 2-stage B, one barrier per chunk ----
    float acc[2][8][4];
    #pragma unroll
    for (int i = 0; i < 2; i++)
        #pragma unroll
        for (int j = 0; j < 8; j++)
            #pragma unroll
            for (int k = 0; k < 4; k++) acc[i][j][k] = 0.f;

    for (int kt = 0; kt < 4; ++kt) {
        asm volatile("cp.async.wait_group 0;\n" ::);
        __syncthreads();
        if (kt < 3) load_B(sb, tid, wsel, kt + 1, (kt + 1) & 1);

        unsigned int bst = sb + B_OFF + (kt & 1) * BSTG;
        #pragma unroll
        for (int ks = 0; ks < 4; ++ks) {
            int kk = kt * 4 + ks;            // absolute 16-wide k-step, 0..15
            unsigned int aH[2][4];
            #pragma unroll
            for (int im = 0; im < 2; ++im) {
                unsigned int ad = sb + A_OFF + (kk >> 1) * ABLK
                    + (unsigned)((wm + im * 16 + (lane & 15)) * 40
                                 + (kk & 1) * 16 + (lane >> 4) * 8) * 2;
                ldm4(aH[im], ad);
            }
            #pragma unroll
            for (int j = 0; j < 4; ++j) {
                unsigned int bd = bst
                    + (unsigned)((ks * 16 + (lane & 15)) * LDB
                                 + wn + j * 16 + (lane >> 4) * 8) * 2;
                unsigned int bh[4];
                ldm4t(bh, bd);
                #pragma unroll
                for (int im = 0; im < 2; ++im) {
                    mma16816(acc[im][2 * j],     aH[im], bh);
                    mma16816(acc[im][2 * j + 1], aH[im], bh + 2);
                }
            }
        }
    }

    // ---- epilogue (register-resident LN) ----
    #pragma unroll
    for (int im = 0; im < 2; ++im)
        #pragma unroll
        for (int jn = 0; jn < 8; ++jn) {
            int c0 = wn + jn * 8 + (lane & 3) * 2;
            float b0 = __ldg(cb + c0), b1 = __ldg(cb + c0 + 1);
            acc[im][jn][0] += b0; acc[im][jn][1] += b1;
            acc[im][jn][2] += b0; acc[im][jn][3] += b1;
        }

    float s1[4] = {0.f, 0.f, 0.f, 0.f}, s2[4] = {0.f, 0.f, 0.f, 0.f};
    #pragma unroll
    for (int jn = 0; jn < 8; ++jn) {
        #pragma unroll
        for (int im = 0; im < 2; ++im) {
            float v0 = acc[im][jn][0], v1 = acc[im][jn][1];
            float v2 = acc[im][jn][2], v3 = acc[im][jn][3];
            s1[im * 2]     += v0 + v1;  s2[im * 2]     += v0 * v0 + v1 * v1;
            s1[im * 2 + 1] += v2 + v3;  s2[im * 2 + 1] += v2 * v2 + v3 * v3;
        }
    }
    #pragma unroll
    for (int t = 0; t < 4; t++) {
        s1[t] += __shfl_xor_sync(0xffffffffu, s1[t], 1);
        s2[t] += __shfl_xor_sync(0xffffffffu, s2[t], 1);
        s1[t] += __shfl_xor_sync(0xffffffffu, s1[t], 2);
        s2[t] += __shfl_xor_sync(0xffffffffu, s2[t], 2);
    }
    int rbase = wm + (lane >> 2);
    if ((lane & 3) == 0) {
        int ng = warp >> 1;
        #pragma unroll
        for (int t = 0; t < 4; t++) {
            st1[ng * 64 + rbase + t * 8] = s1[t];
            st2[ng * 64 + rbase + t * 8] = s2[t];
        }
    }
    __syncthreads();      // also: all warps past mainloop -> A region reusable

    float mu[4], rs[4];
    #pragma unroll
    for (int t = 0; t < 4; t++) {
        int r = rbase + t * 8;
        float a = st1[r] + st1[64 + r] + st1[128 + r] + st1[192 + r];
        float b = st2[r] + st2[64 + r] + st2[128 + r] + st2[192 + r];
        float m = a * (1.f / 256.f);
        mu[t] = m;
        rs[t] = rsqrtf(b * (1.f / 256.f) - m * m + 1e-5f);
    }

    if (mode == 0) {
        // normalize into smem staging (A region), then coalesced uint4 stores
        #pragma unroll
        for (int im = 0; im < 2; ++im) {
            int r0 = wm + im * 16 + (lane >> 2);
            int tA = im * 2, tB = im * 2 + 1;
            #pragma unroll
            for (int jn = 0; jn < 8; ++jn) {
                int c0 = wn + jn * 8 + (lane & 3) * 2;
                float g0 = __ldg(lg + c0), g1 = __ldg(lg + c0 + 1);
                float o0 = __ldg(lb + c0), o1 = __ldg(lb + c0 + 1);
                float v0 = fmaxf((acc[im][jn][0] - mu[tA]) * rs[tA] * g0 + o0, 0.f);
                float v1 = fmaxf((acc[im][jn][1] - mu[tA]) * rs[tA] * g1 + o1, 0.f);
                float v2 = fmaxf((acc[im][jn][2] - mu[tB]) * rs[tB] * g0 + o0, 0.f);
                float v3 = fmaxf((acc[im][jn][3] - mu[tB]) * rs[tB] * g1 + o1, 0.f);
                *(__half2*)(smraw + A_OFF + (r0 * LDB + c0) * 2)       = __floats2half2_rn(v0, v1);
                *(__half2*)(smraw + A_OFF + ((r0 + 8) * LDB + c0) * 2) = __floats2half2_rn(v2, v3);
            }
        }
        __syncthreads();
        #pragma unroll
        for (int i = 0; i < 8; i++) {
            int seg = tid + i * 256;         // 0..2047
            int r2 = seg >> 5, q = seg & 31; // 32 uint4 per row (256 halves)
            uint4 v = *(uint4*)(smraw + A_OFF + (r2 * LDB + q * 8) * 2);
            *(uint4*)(hout + (size_t)(m0 + r2) * HD + q * 8) = v;
        }
    } else {
        // layer 3: column sums of relu(LN(t)) -> g_part
        float cs[16];
        #pragma unroll
        for (int jn = 0; jn < 8; ++jn) {
            int c0 = wn + jn * 8 + (lane & 3) * 2;
            float g0 = __ldg(lg + c0), g1 = __ldg(lg + c0 + 1);
            float o0 = __ldg(lb + c0), o1 = __ldg(lb + c0 + 1);
            float a0 = 0.f, a1 = 0.f;
            #pragma unroll
            for (int im = 0; im < 2; ++im) {
                int tA = im * 2, tB = im * 2 + 1;
                a0 += fmaxf((acc[im][jn][0] - mu[tA]) * rs[tA] * g0 + o0, 0.f)
                    + fmaxf((acc[im][jn][2] - mu[tB]) * rs[tB] * g0 + o0, 0.f);
                a1 += fmaxf((acc[im][jn][1] - mu[tA]) * rs[tA] * g1 + o1, 0.f)
                    + fmaxf((acc[im][jn][3] - mu[tB]) * rs[tB] * g1 + o1, 0.f);
            }
            cs[jn * 2] = a0; cs[jn * 2 + 1] = a1;
        }
        #pragma unroll
        for (int k = 0; k < 16; k++) {
            cs[k] += __shfl_xor_sync(0xffffffffu, cs[k], 4);
            cs[k] += __shfl_xor_sync(0xffffffffu, cs[k], 8);
            cs[k] += __shfl_xor_sync(0xffffffffu, cs[k], 16);
        }
        if (lane < 4) {
            int mg = warp & 1;
            #pragma unroll
            for (int jn = 0; jn < 8; ++jn) {
                int c0 = wn + jn * 8 + lane * 2;
                pool[mg * 256 + c0]     = cs[jn * 2];
                pool[mg * 256 + c0 + 1] = cs[jn * 2 + 1];
            }
        }
        __syncthreads();
        if (tid < 256)
            g_part[(size_t)blockIdx.x * HD + tid] = pool[tid] + pool[256 + tid];
    }
}

// ---------------- MLP head ---------------------------------------------------
__global__ void mlp(const float* __restrict__ w1, const float* __restrict__ b1,
                    const float* __restrict__ w2, const float* __restrict__ b2,
                    float* __restrict__ out) {
    __shared__ float pl[HD], z[HD];
    int b = blockIdx.x, c = threadIdx.x;
    float s = 0.f;
    #pragma unroll 8
    for (int i = 0; i < 64; i++) s += g_part[(size_t)(b * 64 + i) * HD + c];
    pl[c] = s * (1.f / 4096.f);
    __syncthreads();
    float a = b1[c];
    for (int k = 0; k < HD; k++) a += pl[k] * w1[k * HD + c];
    z[c] = fmaxf(a, 0.f);
    __syncthreads();
    float o = b2[c];
    for (int j = 0; j < HD; j++) o += z[j] * w2[j * HD + c];
    out[b * HD + c] = o;
}

// ---------------- launch ------------------------------------------------------
extern "C" void kernel_launch(void* const* d_in, const int* in_sizes, int n_in,
                              void* d_out, int out_size) {
    const float* x      = (const float*)d_in[0];
    const float* proj_w = (const float*)d_in[2];
    const float* proj_b = (const float*)d_in[3];
    const float* conv_w = (const float*)d_in[4];
    const float* conv_b = (const float*)d_in[5];
    const float* ln_g   = (const float*)d_in[6];
    const float* ln_b   = (const float*)d_in[7];
    const float* h1w    = (const float*)d_in[8];
    const float* h1b    = (const float*)d_in[9];
    const float* h2w    = (const float*)d_in[10];
    const float* h2b    = (const float*)d_in[11];
    float* out = (float*)d_out;

    cudaFuncSetAttribute(gemm_fused, cudaFuncAttributeMaxDynamicSharedMemorySize, SMEM_BYTES);

    prep_all<<<1040, 256>>>(proj_w, proj_b, conv_w);
    k0<<<TOTAL / 128, 256>>>(x, conv_b, ln_g, ln_b);   // -> g_ha

    // l=1: g_ha -> g_hb ; l=2: g_hb -> g_ha ; l=3: g_ha -> g_part
    gemm_fused<<<2048, 256, SMEM_BYTES>>>(0, 0, 0, conv_b + 1 * HD, ln_g + 1 * HD, ln_b + 1 * HD);
    gemm_fused<<<2048, 256, SMEM_BYTES>>>(1, 0, 1, conv_b + 2 * HD, ln_g + 2 * HD, ln_b + 2 * HD);
    gemm_fused<<<2048, 256, SMEM_BYTES>>>(2, 1, 0, conv_b + 3 * HD, ln_g + 3 * HD, ln_b + 3 * HD);

    mlp<<<32, 256>>>(h1w, h1b, h2w, h2b, out);
}

// round 17
// speedup vs baseline: 1.1444x; 1.1444x over previous
#include <cuda_runtime.h>
#include <cuda_fp16.h>

#define TOTAL 131072
#define NNODE 4096
#define HD 256

// ---------------- scratch (device globals) ----------------------------------
__device__ __half  g_ha[TOTAL * HD];    // activations, ping
__device__ __half  g_hb[TOTAL * HD];    // activations, pong
__device__ __half  g_wh[3 * HD * HD];   // W (fp16), layers 1..3, layout [k][n]
__device__ float   g_u [HD];            // proj_w @ W0
__device__ float   g_w0[HD];            // proj_b @ W0
__device__ float   g_part[2048 * HD];   // per-block column sums (layer 3)
__device__ float4  g_wt4[NNODE];        // edge weights fp32 (for k0)
__device__ float   g_ws [NNODE];        // self weight fp32 (for k0)
__device__ uint2   g_wph[NNODE];        // edge weights packed fp16 {x,y,z,w}
__device__ __half  g_wsh[NNODE];        // self weight fp16

// ---------------- helpers ----------------------------------------------------
__device__ __forceinline__ float degf(int n) {
    int c = n % 65;
    return (float)(1 + (int)((c != 64) && (n < 4095)) + (int)(c != 0)
                     + (int)(n < 4031) + (int)(n >= 65));
}
__device__ __forceinline__ void cp16ca(unsigned int dst, const void* src) {
    asm volatile("cp.async.ca.shared.global [%0], [%1], 16;\n" :: "r"(dst), "l"(src));
}
__device__ __forceinline__ void ldm4(unsigned int* r, unsigned int a) {
    asm volatile("ldmatrix.sync.aligned.m8n8.x4.shared.b16 {%0,%1,%2,%3}, [%4];\n"
                 : "=r"(r[0]), "=r"(r[1]), "=r"(r[2]), "=r"(r[3]) : "r"(a));
}
__device__ __forceinline__ void ldm4t(unsigned int* r, unsigned int a) {
    asm volatile("ldmatrix.sync.aligned.m8n8.x4.trans.shared.b16 {%0,%1,%2,%3}, [%4];\n"
                 : "=r"(r[0]), "=r"(r[1]), "=r"(r[2]), "=r"(r[3]) : "r"(a));
}
__device__ __forceinline__ void mma16816(float* d, const unsigned int* a, const unsigned int* b) {
    asm volatile(
        "mma.sync.aligned.m16n8k16.row.col.f32.f16.f16.f32 "
        "{%0,%1,%2,%3}, {%4,%5,%6,%7}, {%8,%9}, {%0,%1,%2,%3};\n"
        : "+f"(d[0]), "+f"(d[1]), "+f"(d[2]), "+f"(d[3])
        : "r"(a[0]), "r"(a[1]), "r"(a[2]), "r"(a[3]), "r"(b[0]), "r"(b[1]));
}
// half2 stencil tap: v += w * tap8
__device__ __forceinline__ void sten8(const __half* __restrict__ p, __half2* v, __half2 w) {
    uint4 A = *(const uint4*)p;
    const __half2* ah = (const __half2*)&A;
    v[0] = __hfma2(w, ah[0], v[0]);
    v[1] = __hfma2(w, ah[1], v[1]);
    v[2] = __hfma2(w, ah[2], v[2]);
    v[3] = __hfma2(w, ah[3], v[3]);
}

// ---------------- merged prep kernel ------------------------------------------
__global__ void prep_all(const float* __restrict__ pw, const float* __restrict__ pb,
                         const float* __restrict__ cw) {
    int bid = blockIdx.x;
    if (bid < 256) {
        int c = bid, k = threadIdx.x;
        float wv = cw[k * HD + c];
        float u = pw[k] * wv, w = pb[k] * wv;
        #pragma unroll
        for (int o = 16; o > 0; o >>= 1) {
            u += __shfl_xor_sync(0xffffffffu, u, o);
            w += __shfl_xor_sync(0xffffffffu, w, o);
        }
        __shared__ float ru[8], rw[8];
        int wid = k >> 5;
        if ((k & 31) == 0) { ru[wid] = u; rw[wid] = w; }
        __syncthreads();
        if (k == 0) {
            float tu = 0.f, tw = 0.f;
            #pragma unroll
            for (int i = 0; i < 8; i++) { tu += ru[i]; tw += rw[i]; }
            g_u[c] = tu; g_w0[c] = tw;
        }
    } else if (bid < 1024) {
        int idx = (bid - 256) * 256 + threadIdx.x;
        g_wh[idx] = __float2half_rn(cw[HD * HD + idx]);
    } else {
        int n = (bid - 1024) * 256 + threadIdx.x;
        int col = n % 65;
        float dn = degf(n), dinv = rsqrtf(dn);
        float4 w;
        w.x = (col != 64 && n < 4095) ? dinv * rsqrtf(degf(n + 1))  : 0.f;
        w.y = (col != 0)              ? dinv * rsqrtf(degf(n - 1))  : 0.f;
        w.z = (n < 4031)              ? dinv * rsqrtf(degf(n + 65)) : 0.f;
        w.w = (n >= 65)               ? dinv * rsqrtf(degf(n - 65)) : 0.f;
        g_wt4[n] = w;
        g_ws[n]  = 1.f / dn;
        __half2 lo = __halves2half2(__float2half_rn(w.x), __float2half_rn(w.y));
        __half2 hi = __halves2half2(__float2half_rn(w.z), __float2half_rn(w.w));
        uint2 p;
        p.x = *(unsigned int*)&lo;
        p.y = *(unsigned int*)&hi;
        g_wph[n] = p;
        g_wsh[n] = __float2half_rn(1.f / dn);
    }
}

// ---------------- layer 0: warp handles 16 rows; per-row coeffs lane-parallel
__global__ void __launch_bounds__(256) k0(const float* __restrict__ x,
                                          const float* __restrict__ cb,
                                          const float* __restrict__ lg,
                                          const float* __restrict__ lb) {
    int warp = threadIdx.x >> 5, lane = threadIdx.x & 31;
    int c8 = lane * 8;
    int row0 = blockIdx.x * 128 + warp * 16;

    float ua[8], wa[8], ba[8], ga[8], la[8];
    {
        float4 t0 = *(const float4*)(g_u  + c8), t1 = *(const float4*)(g_u  + c8 + 4);
        ua[0]=t0.x; ua[1]=t0.y; ua[2]=t0.z; ua[3]=t0.w; ua[4]=t1.x; ua[5]=t1.y; ua[6]=t1.z; ua[7]=t1.w;
        t0 = *(const float4*)(g_w0 + c8); t1 = *(const float4*)(g_w0 + c8 + 4);
        wa[0]=t0.x; wa[1]=t0.y; wa[2]=t0.z; wa[3]=t0.w; wa[4]=t1.x; wa[5]=t1.y; wa[6]=t1.z; wa[7]=t1.w;
        t0 = *(const float4*)(cb   + c8); t1 = *(const float4*)(cb   + c8 + 4);
        ba[0]=t0.x; ba[1]=t0.y; ba[2]=t0.z; ba[3]=t0.w; ba[4]=t1.x; ba[5]=t1.y; ba[6]=t1.z; ba[7]=t1.w;
        t0 = *(const float4*)(lg   + c8); t1 = *(const float4*)(lg   + c8 + 4);
        ga[0]=t0.x; ga[1]=t0.y; ga[2]=t0.z; ga[3]=t0.w; ga[4]=t1.x; ga[5]=t1.y; ga[6]=t1.z; ga[7]=t1.w;
        t0 = *(const float4*)(lb   + c8); t1 = *(const float4*)(lb   + c8 + 4);
        la[0]=t0.x; la[1]=t0.y; la[2]=t0.z; la[3]=t0.w; la[4]=t1.x; la[5]=t1.y; la[6]=t1.z; la[7]=t1.w;
    }

    float Av = 0.f, Bv = 0.f;
    if (lane < 16) {
        int row = row0 + lane;
        int n = row & (NNODE - 1);
        float4 wt = g_wt4[n];
        float ws = g_ws[n];
        Av = x[row] * ws; Bv = ws;
        if (wt.x != 0.f) { Av += wt.x * x[row + 1];  Bv += wt.x; }
        if (wt.y != 0.f) { Av += wt.y * x[row - 1];  Bv += wt.y; }
        if (wt.z != 0.f) { Av += wt.z * x[row + 65]; Bv += wt.z; }
        if (wt.w != 0.f) { Av += wt.w * x[row - 65]; Bv += wt.w; }
    }

    #pragma unroll 4
    for (int rr = 0; rr < 16; rr++) {
        int row = row0 + rr;
        float A = __shfl_sync(0xffffffffu, Av, rr);
        float B = __shfl_sync(0xffffffffu, Bv, rr);

        float y[8], s1 = 0.f, s2 = 0.f;
        #pragma unroll
        for (int j = 0; j < 8; j++) {
            y[j] = A * ua[j] + B * wa[j] + ba[j];
            s1 += y[j]; s2 += y[j] * y[j];
        }
        #pragma unroll
        for (int o = 16; o > 0; o >>= 1) {
            s1 += __shfl_xor_sync(0xffffffffu, s1, o);
            s2 += __shfl_xor_sync(0xffffffffu, s2, o);
        }
        float mu  = s1 * (1.f / 256.f);
        float var = s2 * (1.f / 256.f) - mu * mu;
        float rs  = rsqrtf(var + 1e-5f);

        uint4 Hq;
        __half* hp = (__half*)&Hq;
        #pragma unroll
        for (int j = 0; j < 8; j++) {
            float v = fmaxf((y[j] - mu) * rs * ga[j] + la[j], 0.f);
            hp[j] = __float2half_rn(v);
        }
        *(uint4*)(g_ha + (size_t)row * HD + c8) = Hq;
    }
}

// ---------------- fused stencil + GEMM + bias + LN + ReLU (+pool) -----------
// M=64 tile, 256 threads, 8 warps (warp tile 32x64), 2 CTAs/SM.
// A = stencil(hin) in smem (packed HFMA2); B streamed in 8 K-chunks of 32 rows
// via 3-stage cp.async. Epilogue: LN into smem staging + coalesced uint4 stores.
#define A_OFF    0
#define ABLK     5120           /* bytes per 64x40-half A block */
#define B_OFF    40960
#define LDB      264
#define BSTG     16896          /* 32 x 264 halves */
#define ST1_OFF  91648          /* [4][64] floats */
#define ST2_OFF  92672
#define POOL_OFF 93696          /* [2][256] floats */
#define SMEM_BYTES 95744

__device__ __forceinline__ void load_B(unsigned int sb, int tid, int wsel,
                                       int kt, int s) {
    const __half* Bw = g_wh + (size_t)wsel * HD * HD + (size_t)kt * 32 * HD;
    unsigned int st = sb + B_OFF + s * BSTG;
    #pragma unroll
    for (int i = 0; i < 4; i++) {
        int ch = tid + i * 256;            // 0..1023
        int kr = ch >> 5, cg = ch & 31;
        cp16ca(st + (unsigned)(kr * LDB + cg * 8) * 2, Bw + kr * HD + cg * 8);
    }
    asm volatile("cp.async.commit_group;\n" ::);
}

__global__ void __launch_bounds__(256, 2) gemm_fused(int wsel, int mode, int dir,
                                                     const float* __restrict__ cb,
                                                     const float* __restrict__ lg,
                                                     const float* __restrict__ lb) {
    extern __shared__ char smraw[];
    unsigned int sb = (unsigned int)__cvta_generic_to_shared(smraw);
    float* st1  = (float*)(smraw + ST1_OFF);   // [4][64]
    float* st2  = (float*)(smraw + ST2_OFF);   // [4][64]
    float* pool = (float*)(smraw + POOL_OFF);  // [2][256]
    int tid = threadIdx.x, lane = tid & 31, warp = tid >> 5;
    int m0 = blockIdx.x * 64;
    int wm = (warp & 1) * 32, wn = (warp >> 1) * 64;

    const __half* __restrict__ hin = dir ? g_hb : g_ha;
    __half* __restrict__ hout      = dir ? g_ha : g_hb;

    // ---- B pipeline prologue (overlaps with stencil compute below) ----
    load_B(sb, tid, wsel, 0, 0);
    load_B(sb, tid, wsel, 1, 1);

    // ---- A = stencil(hin) into smem, packed fp16 math ----
    #pragma unroll
    for (int i = 0; i < 8; i++) {
        int ch = tid + i * 256;              // 0..2047
        int r = ch >> 5, cg = ch & 31;       // warp-uniform r
        int row = m0 + r;
        int n = row & (NNODE - 1);
        uint2 wp = g_wph[n];
        __half2 wxy = *(__half2*)&wp.x;
        __half2 wzw = *(__half2*)&wp.y;
        size_t cofs = (size_t)cg * 8;
        const __half* hr = hin + (size_t)row * HD + cofs;
        const __half* hx = hin + (size_t)min(row + 1,  TOTAL - 1) * HD + cofs;
        const __half* hy = hin + (size_t)max(row - 1,  0)         * HD + cofs;
        const __half* hz = hin + (size_t)min(row + 65, TOTAL - 1) * HD + cofs;
        const __half* hw = hin + (size_t)max(row - 65, 0)         * HD + cofs;

        __half2 vh[4];
        {
            uint4 A = *(const uint4*)hr;
            const __half2* ah = (const __half2*)&A;
            __half2 w2 = __half2half2(g_wsh[n]);
            vh[0] = __hmul2(w2, ah[0]); vh[1] = __hmul2(w2, ah[1]);
            vh[2] = __hmul2(w2, ah[2]); vh[3] = __hmul2(w2, ah[3]);
        }
        sten8(hx, vh, __half2half2(__low2half(wxy)));
        sten8(hy, vh, __half2half2(__high2half(wxy)));
        sten8(hz, vh, __half2half2(__low2half(wzw)));
        sten8(hw, vh, __half2half2(__high2half(wzw)));

        int kb = cg >> 2, cc = (cg & 3) * 8;
        *(uint4*)(smraw + A_OFF + kb * ABLK + (r * 40 + cc) * 2) = *(uint4*)vh;
    }

    // ---- mainloop: 3-stage B pipeline ----
    float acc[2][8][4];
    #pragma unroll
    for (int i = 0; i < 2; i++)
        #pragma unroll
        for (int j = 0; j < 8; j++)
            #pragma unroll
            for (int k = 0; k < 4; k++) acc[i][j][k] = 0.f;

    for (int kt = 0; kt < 8; ++kt) {
        asm volatile("cp.async.wait_group 1;\n" ::);
        __syncthreads();
        if (kt < 6) load_B(sb, tid, wsel, kt + 2, (kt + 2) % 3);
        else        asm volatile("cp.async.commit_group;\n" ::);

        unsigned int bst = sb + B_OFF + (kt % 3) * BSTG;
        #pragma unroll
        for (int ks = 0; ks < 2; ++ks) {
            unsigned int aH[2][4];
            #pragma unroll
            for (int im = 0; im < 2; ++im) {
                unsigned int ad = sb + A_OFF + kt * ABLK
                    + (unsigned)((wm + im * 16 + (lane & 15)) * 40 + ks * 16 + (lane >> 4) * 8) * 2;
                ldm4(aH[im], ad);
            }
            #pragma unroll
            for (int j = 0; j < 4; ++j) {
                unsigned int bd = bst
                    + (unsigned)((ks * 16 + (lane & 15)) * LDB
                                 + wn + j * 16 + (lane >> 4) * 8) * 2;
                unsigned int bh[4];
                ldm4t(bh, bd);
                #pragma unroll
                for (int im = 0; im < 2; ++im) {
                    mma16816(acc[im][2 * j],     aH[im], bh);
                    mma16816(acc[im][2 * j + 1], aH[im], bh + 2);
                }
            }
        }
    }
    asm volatile("cp.async.wait_group 0;\n" ::);

    // ---- epilogue (register-resident LN) ----
    #pragma unroll
    for (int im = 0; im < 2; ++im)
        #pragma unroll
        for (int jn = 0; jn < 8; ++jn) {
            int c0 = wn + jn * 8 + (lane & 3) * 2;
            float b0 = __ldg(cb + c0), b1 = __ldg(cb + c0 + 1);
            acc[im][jn][0] += b0; acc[im][jn][1] += b1;
            acc[im][jn][2] += b0; acc[im][jn][3] += b1;
        }

    float s1[4] = {0.f, 0.f, 0.f, 0.f}, s2[4] = {0.f, 0.f, 0.f, 0.f};
    #pragma unroll
    for (int jn = 0; jn < 8; ++jn) {
        #pragma unroll
        for (int im = 0; im < 2; ++im) {
            float v0 = acc[im][jn][0], v1 = acc[im][jn][1];
            float v2 = acc[im][jn][2], v3 = acc[im][jn][3];
            s1[im * 2]     += v0 + v1;  s2[im * 2]     += v0 * v0 + v1 * v1;
            s1[im * 2 + 1] += v2 + v3;  s2[im * 2 + 1] += v2 * v2 + v3 * v3;
        }
    }
    #pragma unroll
    for (int t = 0; t < 4; t++) {
        s1[t] += __shfl_xor_sync(0xffffffffu, s1[t], 1);
        s2[t] += __shfl_xor_sync(0xffffffffu, s2[t], 1);
        s1[t] += __shfl_xor_sync(0xffffffffu, s1[t], 2);
        s2[t] += __shfl_xor_sync(0xffffffffu, s2[t], 2);
    }
    int rbase = wm + (lane >> 2);
    if ((lane & 3) == 0) {
        int ng = warp >> 1;
        #pragma unroll
        for (int t = 0; t < 4; t++) {
            st1[ng * 64 + rbase + t * 8] = s1[t];
            st2[ng * 64 + rbase + t * 8] = s2[t];
        }
    }
    __syncthreads();      // stats visible; all warps past mainloop -> A reusable

    float mu[4], rs[4];
    #pragma unroll
    for (int t = 0; t < 4; t++) {
        int r = rbase + t * 8;
        float a = st1[r] + st1[64 + r] + st1[128 + r] + st1[192 + r];
        float b = st2[r] + st2[64 + r] + st2[128 + r] + st2[192 + r];
        float m = a * (1.f / 256.f);
        mu[t] = m;
        rs[t] = rsqrtf(b * (1.f / 256.f) - m * m + 1e-5f);
    }

    if (mode == 0) {
        // normalize into smem staging (A region), then coalesced uint4 stores
        #pragma unroll
        for (int im = 0; im < 2; ++im) {
            int r0 = wm + im * 16 + (lane >> 2);
            int tA = im * 2, tB = im * 2 + 1;
            #pragma unroll
            for (int jn = 0; jn < 8; ++jn) {
                int c0 = wn + jn * 8 + (lane & 3) * 2;
                float g0 = __ldg(lg + c0), g1 = __ldg(lg + c0 + 1);
                float o0 = __ldg(lb + c0), o1 = __ldg(lb + c0 + 1);
                float v0 = fmaxf((acc[im][jn][0] - mu[tA]) * rs[tA] * g0 + o0, 0.f);
                float v1 = fmaxf((acc[im][jn][1] - mu[tA]) * rs[tA] * g1 + o1, 0.f);
                float v2 = fmaxf((acc[im][jn][2] - mu[tB]) * rs[tB] * g0 + o0, 0.f);
                float v3 = fmaxf((acc[im][jn][3] - mu[tB]) * rs[tB] * g1 + o1, 0.f);
                *(__half2*)(smraw + A_OFF + (r0 * LDB + c0) * 2)       = __floats2half2_rn(v0, v1);
                *(__half2*)(smraw + A_OFF + ((r0 + 8) * LDB + c0) * 2) = __floats2half2_rn(v2, v3);
            }
        }
        __syncthreads();
        #pragma unroll
        for (int i = 0; i < 8; i++) {
            int seg = tid + i * 256;         // 0..2047
            int r2 = seg >> 5, q = seg & 31; // 32 uint4 per row (256 halves)
            uint4 v = *(uint4*)(smraw + A_OFF + (r2 * LDB + q * 8) * 2);
            *(uint4*)(hout + (size_t)(m0 + r2) * HD + q * 8) = v;
        }
    } else {
        // layer 3: column sums of relu(LN(t)) -> g_part
        float cs[16];
        #pragma unroll
        for (int jn = 0; jn < 8; ++jn) {
            int c0 = wn + jn * 8 + (lane & 3) * 2;
            float g0 = __ldg(lg + c0), g1 = __ldg(lg + c0 + 1);
            float o0 = __ldg(lb + c0), o1 = __ldg(lb + c0 + 1);
            float a0 = 0.f, a1 = 0.f;
            #pragma unroll
            for (int im = 0; im < 2; ++im) {
                int tA = im * 2, tB = im * 2 + 1;
                a0 += fmaxf((acc[im][jn][0] - mu[tA]) * rs[tA] * g0 + o0, 0.f)
                    + fmaxf((acc[im][jn][2] - mu[tB]) * rs[tB] * g0 + o0, 0.f);
                a1 += fmaxf((acc[im][jn][1] - mu[tA]) * rs[tA] * g1 + o1, 0.f)
                    + fmaxf((acc[im][jn][3] - mu[tB]) * rs[tB] * g1 + o1, 0.f);
            }
            cs[jn * 2] = a0; cs[jn * 2 + 1] = a1;
        }
        #pragma unroll
        for (int k = 0; k < 16; k++) {
            cs[k] += __shfl_xor_sync(0xffffffffu, cs[k], 4);
            cs[k] += __shfl_xor_sync(0xffffffffu, cs[k], 8);
            cs[k] += __shfl_xor_sync(0xffffffffu, cs[k], 16);
        }
        if (lane < 4) {
            int mg = warp & 1;
            #pragma unroll
            for (int jn = 0; jn < 8; ++jn) {
                int c0 = wn + jn * 8 + lane * 2;
                pool[mg * 256 + c0]     = cs[jn * 2];
                pool[mg * 256 + c0 + 1] = cs[jn * 2 + 1];
            }
        }
        __syncthreads();
        if (tid < 256)
            g_part[(size_t)blockIdx.x * HD + tid] = pool[tid] + pool[256 + tid];
    }
}

// ---------------- MLP head ---------------------------------------------------
__global__ void mlp(const float* __restrict__ w1, const float* __restrict__ b1,
                    const float* __restrict__ w2, const float* __restrict__ b2,
                    float* __restrict__ out) {
    __shared__ float pl[HD], z[HD];
    int b = blockIdx.x, c = threadIdx.x;
    float s = 0.f;
    #pragma unroll 8
    for (int i = 0; i < 64; i++) s += g_part[(size_t)(b * 64 + i) * HD + c];
    pl[c] = s * (1.f / 4096.f);
    __syncthreads();
    float a = b1[c];
    for (int k = 0; k < HD; k++) a += pl[k] * w1[k * HD + c];
    z[c] = fmaxf(a, 0.f);
    __syncthreads();
    float o = b2[c];
    for (int j = 0; j < HD; j++) o += z[j] * w2[j * HD + c];
    out[b * HD + c] = o;
}

// ---------------- launch ------------------------------------------------------
extern "C" void kernel_launch(void* const* d_in, const int* in_sizes, int n_in,
                              void* d_out, int out_size) {
    const float* x      = (const float*)d_in[0];
    const float* proj_w = (const float*)d_in[2];
    const float* proj_b = (const float*)d_in[3];
    const float* conv_w = (const float*)d_in[4];
    const float* conv_b = (const float*)d_in[5];
    const float* ln_g   = (const float*)d_in[6];
    const float* ln_b   = (const float*)d_in[7];
    const float* h1w    = (const float*)d_in[8];
    const float* h1b    = (const float*)d_in[9];
    const float* h2w    = (const float*)d_in[10];
    const float* h2b    = (const float*)d_in[11];
    float* out = (float*)d_out;

    cudaFuncSetAttribute(gemm_fused, cudaFuncAttributeMaxDynamicSharedMemorySize, SMEM_BYTES);

    prep_all<<<1040, 256>>>(proj_w, proj_b, conv_w);
    k0<<<TOTAL / 128, 256>>>(x, conv_b, ln_g, ln_b);   // -> g_ha

    // l=1: g_ha -> g_hb ; l=2: g_hb -> g_ha ; l=3: g_ha -> g_part
    gemm_fused<<<2048, 256, SMEM_BYTES>>>(0, 0, 0, conv_b + 1 * HD, ln_g + 1 * HD, ln_b + 1 * HD);
    gemm_fused<<<2048, 256, SMEM_BYTES>>>(1, 0, 1, conv_b + 2 * HD, ln_g + 2 * HD, ln_b + 2 * HD);
    gemm_fused<<<2048, 256, SMEM_BYTES>>>(2, 1, 0, conv_b + 3 * HD, ln_g + 3 * HD, ln_b + 3 * HD);

    mlp<<<32, 256>>>(h1w, h1b, h2w, h2b, out);
}